// round 12
// baseline (speedup 1.0000x reference)
#include <cuda_runtime.h>
#include <cstdint>

typedef unsigned long long ull;

// Problem constants (fixed shapes)
#define BB 2
#define NN 16384
#define MM 8192

// Pair-kernel tiling
#define THREADS 256
#define RP 8                      // packed n-pairs per thread
#define RR (2 * RP)               // 16 n per thread
#define TN (RR * THREADS)         // 4096 n per block
#define NT (NN / TN)              // 4 n-tiles
#define MT 37                     // m-tiles
#define TM 224                    // 37*224 = 8288 >= 8192
#define NWARPS (THREADS / 32)
#define SLOT4 10                  // padded slot row: 10 int4 = 40 ints (>= MT)

#define NEG_BIG -3.0e38f
#define ENC_NEG_INF ((int)0x80000000)

// ---------------- scratch (device globals; slot-per-block, no atomics) --------
__device__ int4   g_s1T[BB * NN][SLOT4]; // side-1 partials, transposed: row per n,
                                         // int n-th row holds slots 0..36 (pad 37..39 unused)
__device__ int    g_s2[NT][BB * MM];     // side-2 partial: per n-tile block, per m
__device__ float4 g_part[128];           // per-block {s0, s1, s2, wm_local}
__device__ unsigned int g_done = 0;      // completion counter (self-resetting)

// Order-preserving float<->int encoding (monotone under signed int compare).
__device__ __forceinline__ int encf(float f) {
    int i = __float_as_int(f);
    return (i >= 0) ? i : (i ^ 0x7FFFFFFF);
}
__device__ __forceinline__ float decf(int k) {
    return __int_as_float((k >= 0) ? k : (k ^ 0x7FFFFFFF));
}

// ---------------- packed f32x2 + redux helpers --------------------------------
__device__ __forceinline__ ull pk2(float lo, float hi) {
    ull r; asm("mov.b64 %0, {%1, %2};" : "=l"(r) : "f"(lo), "f"(hi)); return r;
}
__device__ __forceinline__ void upk2(ull v, float& lo, float& hi) {
    asm("mov.b64 {%0, %1}, %2;" : "=f"(lo), "=f"(hi) : "l"(v));
}
__device__ __forceinline__ ull ffma2(ull a, ull b, ull c) {
    ull d; asm("fma.rn.f32x2 %0, %1, %2, %3;" : "=l"(d) : "l"(a), "l"(b), "l"(c)); return d;
}
__device__ __forceinline__ ull fadd2(ull a, ull b) {
    ull d; asm("add.rn.f32x2 %0, %1, %2;" : "=l"(d) : "l"(a), "l"(b)); return d;
}
// Hardware cross-lane s32 max (sm_80+ baseline).
__device__ __forceinline__ int redux_maxi(int v) {
    int r; asm("redux.sync.max.s32 %0, %1, 0xffffffff;" : "=r"(r) : "r"(v)); return r;
}

// ---------------- kernel 1: pairwise dual-min (pipelined f32x2 + redux) -------
// Hot loop UNCHANGED from R10 — measured at the packed-FMA-pipe roofline.
// Only the side-1 flush changed: transposed scalar stores (g_s1T[n][slot]).
__global__ void __launch_bounds__(THREADS, 2) k_pairs(const float* __restrict__ p1,
                                                      const float* __restrict__ p2) {
    const int b  = blockIdx.z;
    const int nb = blockIdx.y * TN;
    const int mb = blockIdx.x * TM;
    const int tid  = threadIdx.x;
    const int wid  = tid >> 5;
    const int lane = tid & 31;

    __shared__ ulonglong2 smA[TM + 1];   // {xx, yy}; +1 pad: branch-free preload
    __shared__ ulonglong2 smB[TM + 1];   // {zz, ww}  (w = -0.5*|p|^2)
    __shared__ int swm[NWARPS][TM];      // encoded per-warp maxima

    // stage + pack m-tile directly from raw points2 (L2-resident, 2.7KB/block)
    if (tid <= TM) {
        int mg = mb + tid;
        float x = 0.f, y = 0.f, z = 0.f, w2 = NEG_BIG;   // sentinel never wins
        if (tid < TM && mg < MM) {
            const float* p = p2 + ((size_t)b * MM + mg) * 3;
            x = p[0]; y = p[1]; z = p[2];
            w2 = -0.5f * (x * x + y * y + z * z);
        }
        ulonglong2 A, B;
        A.x = pk2(x, x);  A.y = pk2(y, y);
        B.x = pk2(z, z);  B.y = pk2(w2, w2);
        smA[tid] = A; smB[tid] = B;
    }

    // per-thread n registers (packed pairs of consecutive n)
    ull x2[RP], y2[RP], z2[RP], hn2[RP];
    float mx[RR];
#pragma unroll
    for (int p = 0; p < RP; p++) {
        int n0 = nb + (p * THREADS + tid) * 2;           // exact tiling, always < NN
        const float2* q = (const float2*)(p1 + ((size_t)b * NN + n0) * 3);
        float2 a = q[0], bb2 = q[1], cc = q[2];
        float X0 = a.x,  Y0 = a.y,  Z0 = bb2.x;
        float X1 = bb2.y, Y1 = cc.x, Z1 = cc.y;
        x2[p] = pk2(X0, X1);
        y2[p] = pk2(Y0, Y1);
        z2[p] = pk2(Z0, Z1);
        float h0 = 0.5f * (X0 * X0 + Y0 * Y0 + Z0 * Z0);
        float h1 = 0.5f * (X1 * X1 + Y1 * Y1 + Z1 * Z1);
        hn2[p] = pk2(-h0, -h1);
        mx[2 * p] = NEG_BIG; mx[2 * p + 1] = NEG_BIG;
    }
    __syncthreads();

    // software-pipelined j loop: m-point for j+1 loads while j computes
    ulonglong2 A0 = smA[0], B0 = smB[0];
#pragma unroll 2
    for (int j = 0; j < TM; j++) {
        ulonglong2 A1 = smA[j + 1];                      // LDS.128 (pad makes legal)
        ulonglong2 B1 = smB[j + 1];
        ull bx = A0.x, by = A0.y, bz = B0.x, bw = B0.y;
        float wm0 = NEG_BIG, wm1 = NEG_BIG;
#pragma unroll
        for (int p = 0; p < RP; p++) {
            ull c2 = ffma2(x2[p], bx, bw);               // acc init = -h2m
            c2 = ffma2(y2[p], by, c2);
            c2 = ffma2(z2[p], bz, c2);
            ull w2 = fadd2(c2, hn2[p]);                  // c' - h1
            float cl, ch; upk2(c2, cl, ch);              // reg-pair alias (free)
            mx[2 * p]     = fmaxf(mx[2 * p], cl);
            mx[2 * p + 1] = fmaxf(mx[2 * p + 1], ch);
            float wl, wh; upk2(w2, wl, wh);
            wm0 = fmaxf(wm0, wl);
            wm1 = fmaxf(wm1, wh);
        }
        int t = redux_maxi(encf(fmaxf(wm0, wm1)));       // single-op warp max
        if (lane == 0) swm[wid][j] = t;
        A0 = A1; B0 = B1;
    }

    // flush side 1: transposed — per-n tile-max into this block's slot column.
    // 16 scalar stores/thread (stride 160B); tail-hidden behind block stagger.
    {
        const int slot = blockIdx.x;
#pragma unroll
        for (int p = 0; p < RP; p++) {
            int n0 = nb + (p * THREADS + tid) * 2;
            ((int*)&g_s1T[b * NN + n0][0])[slot]     = encf(mx[2 * p]);
            ((int*)&g_s1T[b * NN + n0 + 1][0])[slot] = encf(mx[2 * p + 1]);
        }
    }
    __syncthreads();

    // flush side 2: cross-warp reduce (encoded), write own slot (coalesced)
    for (int j = tid; j < TM; j += THREADS) {
        int mg = mb + j;
        if (mg < MM) {
            int v = swm[0][j];
#pragma unroll
            for (int w = 1; w < NWARPS; w++) v = max(v, swm[w][j]);
            g_s2[blockIdx.y][b * MM + mg] = v;
        }
    }
}

// ---------------- kernel 2: slot reduce (vectorized) + fused final ------------
__global__ void __launch_bounds__(THREADS) k_partial(const float* __restrict__ p1,
                                                     const float* __restrict__ w,
                                                     float* __restrict__ out) {
    const int blk = blockIdx.x;               // 128 blocks
    const int b = blk >> 6;
    const int idx = blk & 63;
    const int tid = threadIdx.x;
    const int lane = tid & 31;
    const int wid = tid >> 5;

    __shared__ float sa[THREADS], sb[THREADS], sc[THREADS];
    __shared__ int swx[NWARPS];

    const int n = idx * 256 + tid;
    const int gn = b * NN + n;

    // ---- front-batched loads: 9 x LDG.128 + 1 scalar covers slots 0..36 ----
    int4 v4[9];
#pragma unroll
    for (int k = 0; k < 9; k++) v4[k] = g_s1T[gn][k];
    int v36 = ((const int*)&g_s1T[gn][0])[36];
    int v2[NT];
    const int gm = b * MM + idx * 128 + (tid & 127);     // valid addr for all tids
#pragma unroll
    for (int k = 0; k < NT; k++) v2[k] = g_s2[k][gm];
    float wv = w[gn];
    const float* p = p1 + (size_t)gn * 3;
    float xx = p[0], yy = p[1], zz = p[2];

    // ---- weight max (overlaps the in-flight loads) ----
    int te = redux_maxi(encf(wv));
    if (lane == 0) swx[wid] = te;
    __syncthreads();
    int wme = swx[0];
#pragma unroll
    for (int k = 1; k < NWARPS; k++) wme = max(wme, swx[k]);
    float wm = decf(wme);

    // ---- side-1 tree reduction: int4 pairwise, then components ----
    int4 r0, r1;
    r0.x = max(v4[0].x, v4[1].x); r0.y = max(v4[0].y, v4[1].y);
    r0.z = max(v4[0].z, v4[1].z); r0.w = max(v4[0].w, v4[1].w);
    r1.x = max(v4[2].x, v4[3].x); r1.y = max(v4[2].y, v4[3].y);
    r1.z = max(v4[2].z, v4[3].z); r1.w = max(v4[2].w, v4[3].w);
    r0.x = max(r0.x, r1.x); r0.y = max(r0.y, r1.y);
    r0.z = max(r0.z, r1.z); r0.w = max(r0.w, r1.w);
    r1.x = max(v4[4].x, v4[5].x); r1.y = max(v4[4].y, v4[5].y);
    r1.z = max(v4[4].z, v4[5].z); r1.w = max(v4[4].w, v4[5].w);
    int4 r2;
    r2.x = max(v4[6].x, v4[7].x); r2.y = max(v4[6].y, v4[7].y);
    r2.z = max(v4[6].z, v4[7].z); r2.w = max(v4[6].w, v4[7].w);
    r1.x = max(r1.x, r2.x); r1.y = max(r1.y, r2.y);
    r1.z = max(r1.z, r2.z); r1.w = max(r1.w, r2.w);
    r0.x = max(r0.x, r1.x); r0.y = max(r0.y, r1.y);
    r0.z = max(r0.z, r1.z); r0.w = max(r0.w, r1.w);
    r0.x = max(r0.x, v4[8].x); r0.y = max(r0.y, v4[8].y);
    r0.z = max(r0.z, v4[8].z); r0.w = max(r0.w, v4[8].w);
    int m1 = max(max(r0.x, r0.y), max(r0.z, max(r0.w, v36)));

    // ---- n side sums ----
    float e = expf(wv - wm);
    float h1 = 0.5f * (xx * xx + yy * yy + zz * zz);
    float md1 = 2.0f * (h1 - decf(m1));
    float s0 = e;
    float s1 = e * md1;

    // ---- side-2 reduction over 4 slots ----
    float s2 = 0.f;
    if (tid < 128) {
        int m2 = max(max(v2[0], v2[1]), max(v2[2], v2[3]));
        s2 = decf(m2);
    }

    sa[tid] = s0; sb[tid] = s1; sc[tid] = s2;
    __syncthreads();
    for (int st = 128; st > 0; st >>= 1) {
        if (tid < st) {
            sa[tid] += sa[tid + st];
            sb[tid] += sb[tid + st];
            sc[tid] += sc[tid + st];
        }
        __syncthreads();
    }

    __shared__ int last;
    if (tid == 0) {
        float4 r; r.x = sa[0]; r.y = sb[0]; r.z = sc[0]; r.w = wm;
        g_part[blk] = r;
        __threadfence();
        unsigned int prev = atomicAdd(&g_done, 1u);
        last = (prev == 127u) ? 1 : 0;
    }
    __syncthreads();
    if (!last) return;
    __threadfence();

    // last block: deterministic fixed-order combine of 128 partials
    float4 gp = make_float4(0.f, 0.f, 0.f, NEG_BIG);
    if (tid < 128) {
        volatile float4* vp = (volatile float4*)&g_part[tid];
        gp.x = vp->x; gp.y = vp->y; gp.z = vp->z; gp.w = vp->w;
    }
    // phase 1: global weight max per batch half
    sa[tid] = gp.w;
    __syncthreads();
    for (int st = 32; st > 0; st >>= 1) {
        if (tid < 128 && (tid & 63) < st) sa[tid] = fmaxf(sa[tid], sa[tid + st]);
        __syncthreads();
    }
    float wmg = (tid < 128) ? sa[(tid >> 6) << 6] : 0.f;
    __syncthreads();
    // phase 2: rescale local-softmax partials to the global max and reduce
    float c0 = 0.f, c1 = 0.f, c2 = 0.f;
    if (tid < 128) {
        float s = expf(gp.w - wmg);
        c0 = gp.x * s; c1 = gp.y * s; c2 = gp.z;
    }
    sa[tid] = c0; sb[tid] = c1; sc[tid] = c2;
    __syncthreads();
    for (int st = 32; st > 0; st >>= 1) {
        if (tid < 128 && (tid & 63) < st) {
            sa[tid] += sa[tid + st];
            sb[tid] += sb[tid + st];
            sc[tid] += sc[tid + st];
        }
        __syncthreads();
    }
    if (tid == 0) {
        float loss = 0.f;
        loss += sb[0]  / sa[0]  + (-2.0f * sc[0]  / (float)MM);
        loss += sb[64] / sa[64] + (-2.0f * sc[64] / (float)MM);
        out[0] = loss / (float)BB;
        g_done = 0;                           // reset for graph replay
    }
}

// ---------------- launch -----------------------------------------------------
extern "C" void kernel_launch(void* const* d_in, const int* in_sizes, int n_in,
                              void* d_out, int out_size) {
    const float* points1 = (const float*)d_in[0];   // (2,16384,3)
    const float* points2 = (const float*)d_in[1];   // (2,8192,3)
    const float* weights = (const float*)d_in[2];   // (2,16384)
    float* out = (float*)d_out;

    k_pairs<<<dim3(MT, NT, BB), THREADS>>>(points1, points2);
    k_partial<<<128, THREADS>>>(points1, weights, out);
}

// round 13
// speedup vs baseline: 1.0833x; 1.0833x over previous
#include <cuda_runtime.h>
#include <cstdint>

typedef unsigned long long ull;

// Problem constants (fixed shapes)
#define BB 2
#define NN 16384
#define MM 8192

// Pair-kernel tiling
#define THREADS 256
#define RP 8                      // packed n-pairs per thread
#define RR (2 * RP)               // 16 n per thread
#define TN (RR * THREADS)         // 4096 n per block
#define NT (NN / TN)              // 4 n-tiles
#define MT 37                     // m-tiles
#define TM 224                    // 37*224 = 8288 >= 8192
#define NWARPS (THREADS / 32)

// k_partial: 512 threads, slots split across two halves
#define PTHREADS 512

#define NEG_BIG -3.0e38f
#define ENC_NEG_INF ((int)0x80000000)

// ---------------- scratch (device globals; slot-per-block, no atomics) --------
__device__ int    g_s1[MT][BB * NN];    // side-1 partial: per m-tile block, per n
__device__ int    g_s2[NT][BB * MM];    // side-2 partial: per n-tile block, per m
__device__ float4 g_part[128];          // per-block {s0, s1, s2, wm_local}
__device__ unsigned int g_done = 0;     // completion counter (self-resetting)

// Order-preserving float<->int encoding (monotone under signed int compare).
__device__ __forceinline__ int encf(float f) {
    int i = __float_as_int(f);
    return (i >= 0) ? i : (i ^ 0x7FFFFFFF);
}
__device__ __forceinline__ float decf(int k) {
    return __int_as_float((k >= 0) ? k : (k ^ 0x7FFFFFFF));
}

// ---------------- packed f32x2 + redux helpers --------------------------------
__device__ __forceinline__ ull pk2(float lo, float hi) {
    ull r; asm("mov.b64 %0, {%1, %2};" : "=l"(r) : "f"(lo), "f"(hi)); return r;
}
__device__ __forceinline__ void upk2(ull v, float& lo, float& hi) {
    asm("mov.b64 {%0, %1}, %2;" : "=f"(lo), "=f"(hi) : "l"(v));
}
__device__ __forceinline__ ull ffma2(ull a, ull b, ull c) {
    ull d; asm("fma.rn.f32x2 %0, %1, %2, %3;" : "=l"(d) : "l"(a), "l"(b), "l"(c)); return d;
}
__device__ __forceinline__ ull fadd2(ull a, ull b) {
    ull d; asm("add.rn.f32x2 %0, %1, %2;" : "=l"(d) : "l"(a), "l"(b)); return d;
}
// Hardware cross-lane s32 max (sm_80+ baseline).
__device__ __forceinline__ int redux_maxi(int v) {
    int r; asm("redux.sync.max.s32 %0, %1, 0xffffffff;" : "=r"(r) : "r"(v)); return r;
}

// ---------------- kernel 1: pairwise dual-min (pipelined f32x2 + redux) -------
// IDENTICAL to the R10 69.7us version (coalesced int2 side-1 flush).
__global__ void __launch_bounds__(THREADS, 2) k_pairs(const float* __restrict__ p1,
                                                      const float* __restrict__ p2) {
    const int b  = blockIdx.z;
    const int nb = blockIdx.y * TN;
    const int mb = blockIdx.x * TM;
    const int tid  = threadIdx.x;
    const int wid  = tid >> 5;
    const int lane = tid & 31;

    __shared__ ulonglong2 smA[TM + 1];   // {xx, yy}; +1 pad: branch-free preload
    __shared__ ulonglong2 smB[TM + 1];   // {zz, ww}  (w = -0.5*|p|^2)
    __shared__ int swm[NWARPS][TM];      // encoded per-warp maxima

    // stage + pack m-tile directly from raw points2 (L2-resident, 2.7KB/block)
    if (tid <= TM) {
        int mg = mb + tid;
        float x = 0.f, y = 0.f, z = 0.f, w2 = NEG_BIG;   // sentinel never wins
        if (tid < TM && mg < MM) {
            const float* p = p2 + ((size_t)b * MM + mg) * 3;
            x = p[0]; y = p[1]; z = p[2];
            w2 = -0.5f * (x * x + y * y + z * z);
        }
        ulonglong2 A, B;
        A.x = pk2(x, x);  A.y = pk2(y, y);
        B.x = pk2(z, z);  B.y = pk2(w2, w2);
        smA[tid] = A; smB[tid] = B;
    }

    // per-thread n registers (packed pairs of consecutive n)
    ull x2[RP], y2[RP], z2[RP], hn2[RP];
    float mx[RR];
#pragma unroll
    for (int p = 0; p < RP; p++) {
        int n0 = nb + (p * THREADS + tid) * 2;           // exact tiling, always < NN
        const float2* q = (const float2*)(p1 + ((size_t)b * NN + n0) * 3);
        float2 a = q[0], bb2 = q[1], cc = q[2];
        float X0 = a.x,  Y0 = a.y,  Z0 = bb2.x;
        float X1 = bb2.y, Y1 = cc.x, Z1 = cc.y;
        x2[p] = pk2(X0, X1);
        y2[p] = pk2(Y0, Y1);
        z2[p] = pk2(Z0, Z1);
        float h0 = 0.5f * (X0 * X0 + Y0 * Y0 + Z0 * Z0);
        float h1 = 0.5f * (X1 * X1 + Y1 * Y1 + Z1 * Z1);
        hn2[p] = pk2(-h0, -h1);
        mx[2 * p] = NEG_BIG; mx[2 * p + 1] = NEG_BIG;
    }
    __syncthreads();

    // software-pipelined j loop: m-point for j+1 loads while j computes
    ulonglong2 A0 = smA[0], B0 = smB[0];
#pragma unroll 2
    for (int j = 0; j < TM; j++) {
        ulonglong2 A1 = smA[j + 1];                      // LDS.128 (pad makes legal)
        ulonglong2 B1 = smB[j + 1];
        ull bx = A0.x, by = A0.y, bz = B0.x, bw = B0.y;
        float wm0 = NEG_BIG, wm1 = NEG_BIG;
#pragma unroll
        for (int p = 0; p < RP; p++) {
            ull c2 = ffma2(x2[p], bx, bw);               // acc init = -h2m
            c2 = ffma2(y2[p], by, c2);
            c2 = ffma2(z2[p], bz, c2);
            ull w2 = fadd2(c2, hn2[p]);                  // c' - h1
            float cl, ch; upk2(c2, cl, ch);              // reg-pair alias (free)
            mx[2 * p]     = fmaxf(mx[2 * p], cl);
            mx[2 * p + 1] = fmaxf(mx[2 * p + 1], ch);
            float wl, wh; upk2(w2, wl, wh);
            wm0 = fmaxf(wm0, wl);
            wm1 = fmaxf(wm1, wh);
        }
        int t = redux_maxi(encf(fmaxf(wm0, wm1)));       // single-op warp max
        if (lane == 0) swm[wid][j] = t;
        A0 = A1; B0 = B1;
    }

    // flush side 1: per-n tile-max -> own slot (plain coalesced ST.64, no atomics)
#pragma unroll
    for (int p = 0; p < RP; p++) {
        int n0 = nb + (p * THREADS + tid) * 2;
        int2 v; v.x = encf(mx[2 * p]); v.y = encf(mx[2 * p + 1]);
        *reinterpret_cast<int2*>(&g_s1[blockIdx.x][b * NN + n0]) = v;
    }
    __syncthreads();

    // flush side 2: cross-warp reduce (encoded), write own slot
    for (int j = tid; j < TM; j += THREADS) {
        int mg = mb + j;
        if (mg < MM) {
            int v = swm[0][j];
#pragma unroll
            for (int w = 1; w < NWARPS; w++) v = max(v, swm[w][j]);
            g_s2[blockIdx.y][b * MM + mg] = v;
        }
    }
}

// ---------------- kernel 2: slot reduce (split halves) + fused final ----------
// 128 blocks x 512 threads. Half 0 (tid<256) reduces slots 0..18 for n;
// half 1 reduces slots 19..36 for the same n; merged via one smem hop.
__global__ void __launch_bounds__(PTHREADS) k_partial(const float* __restrict__ p1,
                                                      const float* __restrict__ w,
                                                      float* __restrict__ out) {
    const int blk = blockIdx.x;               // 128 blocks
    const int b = blk >> 6;
    const int idx = blk & 63;
    const int tid = threadIdx.x;              // 0..511
    const int nl = tid & 255;                 // n within block
    const int half = tid >> 8;                // 0 or 1

    __shared__ int   sm1[PTHREADS];           // per-half slot maxima
    __shared__ int   sm2[PTHREADS];           // side-2 per-(m,slot)
    __shared__ float sa[PTHREADS], sb[PTHREADS], sc[PTHREADS];
    __shared__ int   swx[8];

    const int n = idx * 256 + nl;
    const int gn = b * NN + n;

    // ---- front-batched slot loads: <=19 per thread, full MLP ----
    int acc = ENC_NEG_INF;
    {
        int v[19];
#pragma unroll
        for (int k = 0; k < 19; k++) {
            int slot = half * 19 + k;
            v[k] = (slot < MT) ? g_s1[slot][gn] : ENC_NEG_INF;
        }
#pragma unroll
        for (int k = 16; k < 19; k++) v[k - 16] = max(v[k - 16], v[k]);
#pragma unroll
        for (int s = 8; s > 0; s >>= 1)
#pragma unroll
            for (int k = 0; k < s; k++) v[k] = max(v[k], v[k + s]);
        acc = v[0];
    }
    // side 2: exactly one load/thread (128 m x 4 slots = 512 threads)
    const int gm = b * MM + idx * 128 + (tid & 127);
    int v2 = g_s2[tid >> 7][gm];
    // n-side inputs (half 0 only)
    float wv = 0.f, xx = 0.f, yy = 0.f, zz = 0.f;
    if (half == 0) {
        wv = w[gn];
        const float* p = p1 + (size_t)gn * 3;
        xx = p[0]; yy = p[1]; zz = p[2];
    }

    sm1[tid] = acc;
    sm2[tid] = v2;
    // block-local weight max over 256 n (held by half-0 warps 0..7)
    if (half == 0) {
        int te = redux_maxi(encf(wv));
        if ((tid & 31) == 0) swx[tid >> 5] = te;
    }
    __syncthreads();
    int wme = swx[0];
#pragma unroll
    for (int k = 1; k < 8; k++) wme = max(wme, swx[k]);
    float wm = decf(wme);

    // ---- combine halves + per-block sums ----
    float s0 = 0.f, s1 = 0.f, s2 = 0.f;
    if (half == 0) {
        int m1 = max(sm1[nl], sm1[nl + 256]);
        float e = expf(wv - wm);
        float h1 = 0.5f * (xx * xx + yy * yy + zz * zz);
        s0 = e;
        s1 = e * (2.0f * (h1 - decf(m1)));
    }
    if (tid < 128) {
        int m2 = max(max(sm2[tid], sm2[tid + 128]),
                     max(sm2[tid + 256], sm2[tid + 384]));
        s2 = decf(m2);
    }

    sa[tid] = s0; sb[tid] = s1; sc[tid] = s2;
    __syncthreads();
    for (int st = 256; st > 0; st >>= 1) {
        if (tid < st) {
            sa[tid] += sa[tid + st];
            sb[tid] += sb[tid + st];
            sc[tid] += sc[tid + st];
        }
        __syncthreads();
    }

    __shared__ int last;
    if (tid == 0) {
        float4 r; r.x = sa[0]; r.y = sb[0]; r.z = sc[0]; r.w = wm;
        g_part[blk] = r;
        __threadfence();
        unsigned int prev = atomicAdd(&g_done, 1u);
        last = (prev == 127u) ? 1 : 0;
    }
    __syncthreads();
    if (!last) return;
    __threadfence();

    // last block: deterministic fixed-order combine of 128 partials
    float4 gp = make_float4(0.f, 0.f, 0.f, NEG_BIG);
    if (tid < 128) {
        volatile float4* vp = (volatile float4*)&g_part[tid];
        gp.x = vp->x; gp.y = vp->y; gp.z = vp->z; gp.w = vp->w;
    }
    // phase 1: global weight max per batch half
    sa[tid] = gp.w;
    __syncthreads();
    for (int st = 32; st > 0; st >>= 1) {
        if (tid < 128 && (tid & 63) < st) sa[tid] = fmaxf(sa[tid], sa[tid + st]);
        __syncthreads();
    }
    float wmg = (tid < 128) ? sa[(tid >> 6) << 6] : 0.f;
    __syncthreads();
    // phase 2: rescale local-softmax partials to the global max and reduce
    float c0 = 0.f, c1 = 0.f, c2 = 0.f;
    if (tid < 128) {
        float s = expf(gp.w - wmg);
        c0 = gp.x * s; c1 = gp.y * s; c2 = gp.z;
    }
    sa[tid] = c0; sb[tid] = c1; sc[tid] = c2;
    __syncthreads();
    for (int st = 32; st > 0; st >>= 1) {
        if (tid < 128 && (tid & 63) < st) {
            sa[tid] += sa[tid + st];
            sb[tid] += sb[tid + st];
            sc[tid] += sc[tid + st];
        }
        __syncthreads();
    }
    if (tid == 0) {
        float loss = 0.f;
        loss += sb[0]  / sa[0]  + (-2.0f * sc[0]  / (float)MM);
        loss += sb[64] / sa[64] + (-2.0f * sc[64] / (float)MM);
        out[0] = loss / (float)BB;
        g_done = 0;                           // reset for graph replay
    }
}

// ---------------- launch -----------------------------------------------------
extern "C" void kernel_launch(void* const* d_in, const int* in_sizes, int n_in,
                              void* d_out, int out_size) {
    const float* points1 = (const float*)d_in[0];   // (2,16384,3)
    const float* points2 = (const float*)d_in[1];   // (2,8192,3)
    const float* weights = (const float*)d_in[2];   // (2,16384)
    float* out = (float*)d_out;

    k_pairs<<<dim3(MT, NT, BB), THREADS>>>(points1, points2);
    k_partial<<<128, PTHREADS>>>(points1, weights, out);
}

// round 14
// speedup vs baseline: 1.0907x; 1.0069x over previous
#include <cuda_runtime.h>
#include <cstdint>

typedef unsigned long long ull;

// Problem constants (fixed shapes)
#define BB 2
#define NN 16384
#define MM 8192

// Pair-kernel tiling
#define THREADS 256
#define RP 8                      // packed n-pairs per thread
#define RR (2 * RP)               // 16 n per thread
#define TN (RR * THREADS)         // 4096 n per block
#define NT (NN / TN)              // 4 n-tiles
#define MT 37                     // m-tiles
#define TM 224                    // 37*224 = 8288 >= 8192
#define NWARPS (THREADS / 32)

// k_partial: 256 blocks x 256 threads
#define PBLKS 256

#define NEG_BIG -3.0e38f
#define ENC_NEG_INF ((int)0x80000000)

// ---------------- scratch (device globals; slot-per-block, no atomics) --------
__device__ int    g_s1[MT][BB * NN];    // side-1: per m-tile block, per n: max_m(w)
__device__ int    g_s2[NT][BB * MM];    // side-2: per n-tile block, per m: max_n(w)
__device__ float4 g_part[PBLKS];        // per-block {s0, s1, s2, wm_local}
__device__ unsigned int g_done = 0;     // completion counter (self-resetting)

// Order-preserving float<->int encoding (monotone under signed int compare).
__device__ __forceinline__ int encf(float f) {
    int i = __float_as_int(f);
    return (i >= 0) ? i : (i ^ 0x7FFFFFFF);
}
__device__ __forceinline__ float decf(int k) {
    return __int_as_float((k >= 0) ? k : (k ^ 0x7FFFFFFF));
}

// ---------------- packed f32x2 + redux helpers --------------------------------
__device__ __forceinline__ ull pk2(float lo, float hi) {
    ull r; asm("mov.b64 %0, {%1, %2};" : "=l"(r) : "f"(lo), "f"(hi)); return r;
}
__device__ __forceinline__ void upk2(ull v, float& lo, float& hi) {
    asm("mov.b64 {%0, %1}, %2;" : "=f"(lo), "=f"(hi) : "l"(v));
}
__device__ __forceinline__ ull ffma2(ull a, ull b, ull c) {
    ull d; asm("fma.rn.f32x2 %0, %1, %2, %3;" : "=l"(d) : "l"(a), "l"(b), "l"(c)); return d;
}
__device__ __forceinline__ ull fadd2(ull a, ull b) {
    ull d; asm("add.rn.f32x2 %0, %1, %2;" : "=l"(d) : "l"(a), "l"(b)); return d;
}
// Hardware cross-lane s32 max (sm_80+ baseline).
__device__ __forceinline__ int redux_maxi(int v) {
    int r; asm("redux.sync.max.s32 %0, %1, 0xffffffff;" : "=r"(r) : "r"(v)); return r;
}

// ---------------- kernel 1: pairwise dual-min (pipelined f32x2 + redux) -------
// Hot loop identical to the R10/R13 roofline version. Side-1 flush now folds
// -h1 so slots hold max_m(dot - h1 - h2) and k_partial needs no points1.
__global__ void __launch_bounds__(THREADS, 2) k_pairs(const float* __restrict__ p1,
                                                      const float* __restrict__ p2) {
    const int b  = blockIdx.z;
    const int nb = blockIdx.y * TN;
    const int mb = blockIdx.x * TM;
    const int tid  = threadIdx.x;
    const int wid  = tid >> 5;
    const int lane = tid & 31;

    __shared__ ulonglong2 smA[TM + 1];   // {xx, yy}; +1 pad: branch-free preload
    __shared__ ulonglong2 smB[TM + 1];   // {zz, ww}  (w = -0.5*|p|^2)
    __shared__ int swm[NWARPS][TM];      // encoded per-warp maxima

    // stage + pack m-tile directly from raw points2 (L2-resident, 2.7KB/block)
    if (tid <= TM) {
        int mg = mb + tid;
        float x = 0.f, y = 0.f, z = 0.f, w2 = NEG_BIG;   // sentinel never wins
        if (tid < TM && mg < MM) {
            const float* p = p2 + ((size_t)b * MM + mg) * 3;
            x = p[0]; y = p[1]; z = p[2];
            w2 = -0.5f * (x * x + y * y + z * z);
        }
        ulonglong2 A, B;
        A.x = pk2(x, x);  A.y = pk2(y, y);
        B.x = pk2(z, z);  B.y = pk2(w2, w2);
        smA[tid] = A; smB[tid] = B;
    }

    // per-thread n registers (packed pairs of consecutive n)
    ull x2[RP], y2[RP], z2[RP], hn2[RP];
    float mx[RR];
#pragma unroll
    for (int p = 0; p < RP; p++) {
        int n0 = nb + (p * THREADS + tid) * 2;           // exact tiling, always < NN
        const float2* q = (const float2*)(p1 + ((size_t)b * NN + n0) * 3);
        float2 a = q[0], bb2 = q[1], cc = q[2];
        float X0 = a.x,  Y0 = a.y,  Z0 = bb2.x;
        float X1 = bb2.y, Y1 = cc.x, Z1 = cc.y;
        x2[p] = pk2(X0, X1);
        y2[p] = pk2(Y0, Y1);
        z2[p] = pk2(Z0, Z1);
        float h0 = 0.5f * (X0 * X0 + Y0 * Y0 + Z0 * Z0);
        float h1 = 0.5f * (X1 * X1 + Y1 * Y1 + Z1 * Z1);
        hn2[p] = pk2(-h0, -h1);
        mx[2 * p] = NEG_BIG; mx[2 * p + 1] = NEG_BIG;
    }
    __syncthreads();

    // software-pipelined j loop: m-point for j+1 loads while j computes
    ulonglong2 A0 = smA[0], B0 = smB[0];
#pragma unroll 2
    for (int j = 0; j < TM; j++) {
        ulonglong2 A1 = smA[j + 1];                      // LDS.128 (pad makes legal)
        ulonglong2 B1 = smB[j + 1];
        ull bx = A0.x, by = A0.y, bz = B0.x, bw = B0.y;
        float wm0 = NEG_BIG, wm1 = NEG_BIG;
#pragma unroll
        for (int p = 0; p < RP; p++) {
            ull c2 = ffma2(x2[p], bx, bw);               // acc init = -h2m
            c2 = ffma2(y2[p], by, c2);
            c2 = ffma2(z2[p], bz, c2);
            ull w2 = fadd2(c2, hn2[p]);                  // dot - h2 - h1
            float cl, ch; upk2(c2, cl, ch);              // reg-pair alias (free)
            mx[2 * p]     = fmaxf(mx[2 * p], cl);
            mx[2 * p + 1] = fmaxf(mx[2 * p + 1], ch);
            float wl, wh; upk2(w2, wl, wh);
            wm0 = fmaxf(wm0, wl);
            wm1 = fmaxf(wm1, wh);
        }
        int t = redux_maxi(encf(fmaxf(wm0, wm1)));       // single-op warp max
        if (lane == 0) swm[wid][j] = t;
        A0 = A1; B0 = B1;
    }

    // flush side 1: fold -h1 (so slot = max_m(dot - h1 - h2)); coalesced ST.64
#pragma unroll
    for (int p = 0; p < RP; p++) {
        int n0 = nb + (p * THREADS + tid) * 2;
        float hL, hH; upk2(hn2[p], hL, hH);
        int2 v; v.x = encf(mx[2 * p] + hL); v.y = encf(mx[2 * p + 1] + hH);
        *reinterpret_cast<int2*>(&g_s1[blockIdx.x][b * NN + n0]) = v;
    }
    __syncthreads();

    // flush side 2: cross-warp reduce (encoded), write own slot
    for (int j = tid; j < TM; j += THREADS) {
        int mg = mb + j;
        if (mg < MM) {
            int v = swm[0][j];
#pragma unroll
            for (int w = 1; w < NWARPS; w++) v = max(v, swm[w][j]);
            g_s2[blockIdx.y][b * MM + mg] = v;
        }
    }
}

// ---------------- kernel 2: slot reduce + fused final -------------------------
// 256 blocks x 256 threads. Per block: 128 n (2 threads/n, ~19 slots each)
// and 64 m (1 load/thread over 4 slots). min_dist = -2 * slot-max for BOTH sides.
__global__ void __launch_bounds__(THREADS) k_partial(const float* __restrict__ w,
                                                     float* __restrict__ out) {
    const int blk = blockIdx.x;               // 0..255
    const int b   = blk >> 7;                 // batch
    const int idx = blk & 127;                // chunk within batch
    const int tid = threadIdx.x;
    const int lane = tid & 31;
    const int wid  = tid >> 5;
    const int nl   = tid & 127;               // n within chunk
    const int half = tid >> 7;                // slot half (0/1)

    __shared__ int   sm1[THREADS];
    __shared__ int   sm2[THREADS];
    __shared__ float sA[NWARPS], sB[NWARPS], sC[NWARPS];
    __shared__ int   swx[4];
    __shared__ float sa[THREADS], sb[THREADS], sc[THREADS];

    const int gn = b * NN + idx * 128 + nl;

    // ---- front-batched slot loads: <=19 per thread ----
    int acc;
    {
        int v[19];
#pragma unroll
        for (int k = 0; k < 19; k++) {
            int slot = half * 19 + k;
            v[k] = (slot < MT) ? g_s1[slot][gn] : ENC_NEG_INF;
        }
#pragma unroll
        for (int k = 16; k < 19; k++) v[k - 16] = max(v[k - 16], v[k]);
#pragma unroll
        for (int s = 8; s > 0; s >>= 1)
#pragma unroll
            for (int k = 0; k < s; k++) v[k] = max(v[k], v[k + s]);
        acc = v[0];
    }
    // side 2: one load/thread: 64 m x 4 slots
    const int gm = b * MM + idx * 64 + (tid & 63);
    int v2 = g_s2[tid >> 6][gm];
    float wv = 0.f;
    if (half == 0) wv = w[gn];

    sm1[tid] = acc;
    sm2[tid] = v2;
    if (half == 0) {                           // warps 0..3 hold the 128 n
        int te = redux_maxi(encf(wv));
        if (lane == 0) swx[wid] = te;
    }
    __syncthreads();
    int wme = max(max(swx[0], swx[1]), max(swx[2], swx[3]));
    float wm = decf(wme);

    // ---- per-thread contributions ----
    float s0 = 0.f, s1 = 0.f, s2 = 0.f;
    if (half == 0) {
        int m1 = max(sm1[nl], sm1[nl + 128]);
        float e = expf(wv - wm);
        s0 = e;
        s1 = e * (-2.0f * decf(m1));           // min_dist1 = -2 * max_m(w)
    }
    if (tid < 64) {
        int m2 = max(max(sm2[tid], sm2[tid + 64]),
                     max(sm2[tid + 128], sm2[tid + 192]));
        s2 = decf(m2);
    }

    // ---- warp shfl sums + one smem hop ----
#pragma unroll
    for (int off = 16; off > 0; off >>= 1) {
        s0 += __shfl_xor_sync(0xffffffffu, s0, off);
        s1 += __shfl_xor_sync(0xffffffffu, s1, off);
        s2 += __shfl_xor_sync(0xffffffffu, s2, off);
    }
    if (lane == 0) { sA[wid] = s0; sB[wid] = s1; sC[wid] = s2; }
    __syncthreads();

    __shared__ int last;
    if (tid == 0) {
        float a = 0.f, bb = 0.f, c = 0.f;
#pragma unroll
        for (int k = 0; k < NWARPS; k++) { a += sA[k]; bb += sB[k]; c += sC[k]; }
        float4 r; r.x = a; r.y = bb; r.z = c; r.w = wm;
        g_part[blk] = r;
        __threadfence();
        unsigned int prev = atomicAdd(&g_done, 1u);
        last = (prev == PBLKS - 1) ? 1 : 0;
    }
    __syncthreads();
    if (!last) return;
    __threadfence();

    // ---- last block: deterministic combine of 256 partials (128/batch) ----
    float4 gp;
    {
        volatile float4* vp = (volatile float4*)&g_part[tid];
        gp.x = vp->x; gp.y = vp->y; gp.z = vp->z; gp.w = vp->w;
    }
    // phase 1: per-batch global weight max (tid>>7 = batch)
    sa[tid] = gp.w;
    __syncthreads();
    for (int st = 64; st > 0; st >>= 1) {
        if ((tid & 127) < st) sa[tid] = fmaxf(sa[tid], sa[tid + st]);
        __syncthreads();
    }
    float wmg = sa[(tid >> 7) << 7];
    __syncthreads();
    // phase 2: rescale local-softmax partials to the global max and reduce
    float s = expf(gp.w - wmg);
    sa[tid] = gp.x * s; sb[tid] = gp.y * s; sc[tid] = gp.z;
    __syncthreads();
    for (int st = 64; st > 0; st >>= 1) {
        if ((tid & 127) < st) {
            sa[tid] += sa[tid + st];
            sb[tid] += sb[tid + st];
            sc[tid] += sc[tid + st];
        }
        __syncthreads();
    }
    if (tid == 0) {
        float loss = 0.f;
        loss += sb[0]   / sa[0]   + (-2.0f * sc[0]   / (float)MM);
        loss += sb[128] / sa[128] + (-2.0f * sc[128] / (float)MM);
        out[0] = loss / (float)BB;
        g_done = 0;                           // reset for graph replay
    }
}

// ---------------- launch -----------------------------------------------------
extern "C" void kernel_launch(void* const* d_in, const int* in_sizes, int n_in,
                              void* d_out, int out_size) {
    const float* points1 = (const float*)d_in[0];   // (2,16384,3)
    const float* points2 = (const float*)d_in[1];   // (2,8192,3)
    const float* weights = (const float*)d_in[2];   // (2,16384)
    float* out = (float*)d_out;

    k_pairs<<<dim3(MT, NT, BB), THREADS>>>(points1, points2);
    k_partial<<<PBLKS, THREADS>>>(weights, out);
}